// round 15
// baseline (speedup 1.0000x reference)
#include <cuda_runtime.h>
#include <math.h>

#define HW 16384
#define NPIX 8388608
#define H2 126
#define HW126 15876
#define N2 8128512        // 512*126*126
#define NH2 8064          // 126*64 half-spectrum per image
#define NHALF 4128768     // 512*8064
#define BN_SC 0.9999950000374997f
#define ATT_SCALE 0.35355339059327373f

typedef unsigned long long ull;

__device__ __forceinline__ ull pk2(float lo, float hi) {
    ull r; asm("mov.b64 %0, {%1, %2};" : "=l"(r) : "f"(lo), "f"(hi)); return r;
}
__device__ __forceinline__ void upk2(ull v, float& lo, float& hi) {
    asm("mov.b64 {%0, %1}, %2;" : "=f"(lo), "=f"(hi) : "l"(v));
}
__device__ __forceinline__ ull fma2(ull a, ull b, ull c) {
    ull d; asm("fma.rn.f32x2 %0, %1, %2, %3;" : "=l"(d) : "l"(a), "l"(b), "l"(c)); return d;
}

__device__ float g_buf1[NPIX];
__device__ float g_buf2[NPIX];
__device__ float g_buf3[NPIX];
__device__ float g_qkv[3 * NPIX];
__device__ float g_xc[N2];
__device__ float g_Are[N2];   // reused as post-conv output (needs N2)
__device__ float g_Aim[NHALF];
__device__ float g_Bre[N2];   // reused as maxpool output (needs 8000000)
__device__ float g_Bim[NHALF];
__device__ float g_Wre[HW126];
__device__ float g_Wim[HW126];
__device__ float g_rpb[8 * 64 * 64];
__device__ float g_wpack[64 * 576];
__device__ float g_bpack[64];

__global__ void init_w126_k() {
    int i = blockIdx.x * blockDim.x + threadIdx.x;
    if (i >= HW126) return;
    int k = i / H2, n = i % H2;
    int t = (k * n) % H2;
    float s, c;
    sincospif(-2.0f * (float)t / 126.0f, &s, &c);
    g_Wre[i] = c; g_Wim[i] = s;
}

__global__ void init_rpb_k(const float* __restrict__ table, const int* __restrict__ relidx) {
    int i = blockIdx.x * blockDim.x + threadIdx.x;
    if (i >= 8 * 4096) return;
    int h = i / 4096, ij = i % 4096;
    g_rpb[i] = table[relidx[ij] * 8 + h];
}

__global__ void pack_gabor_k(const float* __restrict__ fc, const float* __restrict__ fs,
                             const float* __restrict__ b1, const float* __restrict__ b2) {
    int i = blockIdx.x * 256 + threadIdx.x;
    if (i < 32 * 576) { g_wpack[i] = fc[i]; g_wpack[18432 + i] = fs[i]; }
    if (i < 32) { g_bpack[i] = b1[i]; g_bpack[32 + i] = b2[i]; }
}

// ---------- 3x3 conv stride 1: 64x32 out tile, 8 co x (2x4) px per thread ----------
// f32x2: pair across py; weights pre-duplicated (w,w) as u64 in smem, LDS.64 broadcast.
#define TW 68            // smem row stride (16B aligned, 34 rows)
__global__ void __launch_bounds__(256, 2)
conv3x3s1_k(const float* __restrict__ in, const float* __restrict__ wt,
            const float* __restrict__ gamma, const float* __restrict__ beta,
            const float* __restrict__ prev, float* __restrict__ out,
            int CoutW, int Cout_buf, int Hin, int Win, int Hout, int Wout,
            int pad, int act, int useBN) {
    __shared__ __align__(16) float sx[2][34 * TW];
    __shared__ __align__(16) ull swu[64 * 9 * 8];   // (w,w) pairs, [ci][tap][g]
    int ng = CoutW >> 3;
    int b = blockIdx.z / ng;
    int co0 = (blockIdx.z % ng) << 3;
    int tx = threadIdx.x, ty = threadIdx.y;
    int tid = ty * 16 + tx;
    {
        float* swf = reinterpret_cast<float*>(swu);
        for (int i = tid; i < 8 * 64 * 9; i += 256) {
            int g = i / 576, r = i % 576;          // r = ci*9 + tap
            float w = wt[co0 * 576 + i];
            swf[(r * 8 + g) * 2] = w;
            swf[(r * 8 + g) * 2 + 1] = w;
        }
    }
    int ox0 = blockIdx.x * 64, oy0 = blockIdx.y * 32;
    int ix0 = ox0 - pad, iy0 = oy0 - pad;
    ull acc2[8][4];
#pragma unroll
    for (int g = 0; g < 8; g++)
#pragma unroll
        for (int p = 0; p < 4; p++) acc2[g][p] = 0ULL;
    const float* inp0 = in + (size_t)b * 64 * Hin * Win;
    for (int i = tid; i < 34 * TW; i += 256) {
        int rr = i / TW, cc = i % TW;
        int r = iy0 + rr, c = ix0 + cc;
        sx[0][i] = (cc < 66 && r >= 0 && r < Hin && c >= 0 && c < Win)
                       ? inp0[(size_t)r * Win + c] : 0.f;
    }
    __syncthreads();
    int rb = ty * 2, cb = tx * 4;
    for (int ci = 0; ci < 64; ci++) {
        int cur = ci & 1;
        if (ci < 63) {
            const float* inp = inp0 + (size_t)(ci + 1) * Hin * Win;
            for (int i = tid; i < 34 * TW; i += 256) {
                int rr = i / TW, cc = i % TW;
                int r = iy0 + rr, c = ix0 + cc;
                sx[cur ^ 1][i] = (cc < 66 && r >= 0 && r < Hin && c >= 0 && c < Win)
                                     ? inp[(size_t)r * Win + c] : 0.f;
            }
        }
        float xr[4][6];
#pragma unroll
        for (int a = 0; a < 4; a++) {
            const float* rowp = &sx[cur][(rb + a) * TW + cb];
            float4 v4 = *reinterpret_cast<const float4*>(rowp);
            float2 v2 = *reinterpret_cast<const float2*>(rowp + 4);
            xr[a][0] = v4.x; xr[a][1] = v4.y; xr[a][2] = v4.z; xr[a][3] = v4.w;
            xr[a][4] = v2.x; xr[a][5] = v2.y;
        }
        const ull* wb_ = &swu[ci * 72];
#pragma unroll
        for (int ky = 0; ky < 3; ky++) {
            ull vp[6];
#pragma unroll
            for (int c = 0; c < 6; c++) vp[c] = pk2(xr[ky][c], xr[ky + 1][c]);
#pragma unroll
            for (int kx = 0; kx < 3; kx++) {
#pragma unroll
                for (int g = 0; g < 8; g++) {
                    ull w = wb_[(ky * 3 + kx) * 8 + g];
#pragma unroll
                    for (int px = 0; px < 4; px++)
                        acc2[g][px] = fma2(vp[px + kx], w, acc2[g][px]);
                }
            }
        }
        __syncthreads();
    }
#pragma unroll
    for (int g = 0; g < 8; g++) {
        int co = co0 + g;
        float sA = 1.f, sB = 0.f;
        if (useBN) { sA = gamma[co] * BN_SC; sB = beta[co]; }
        else if (beta) sB = beta[co];
#pragma unroll
        for (int px = 0; px < 4; px++) {
            float v0, v1;
            upk2(acc2[g][px], v0, v1);
#pragma unroll
            for (int py = 0; py < 2; py++) {
                float v = (py == 0) ? v0 : v1;
                int oy = oy0 + rb + py, ox = ox0 + cb + px;
                if (oy < Hout && ox < Wout) {
                    v = v * sA + sB;
                    if (act == 1) v = fmaxf(v, 0.f);
                    else if (act == 2) v = fminf(fmaxf(v, 0.f), 6.f);
                    size_t oi = (size_t)(b * Cout_buf + co) * Hout * Wout +
                                (size_t)oy * Wout + ox;
                    if (prev) v += prev[oi];
                    out[oi] = v;
                }
            }
        }
    }
}

// ---------- 3x3 conv stride 2 (w_gc), 8 co/block, transposed weights ----------
__global__ void __launch_bounds__(256, 2)
conv3x3s2_k(const float* __restrict__ in, const float* __restrict__ wt,
            const float* __restrict__ beta, float* __restrict__ out,
            int Hin, int Hout) {
    __shared__ __align__(16) float sw[64 * 9 * 8];   // [ci][tap][g]  (declared first: 16B base)
    __shared__ __align__(16) float sx[65 * 65 + 3];  // padded to keep others aligned
    int b = blockIdx.z >> 3;
    int co0 = (blockIdx.z & 7) << 3;
    int tid = threadIdx.y * 16 + threadIdx.x;
    for (int i = tid; i < 8 * 64 * 9; i += 256) {
        int g = i / 576, r = i % 576;
        sw[r * 8 + g] = wt[co0 * 576 + i];
    }
    int ox0 = blockIdx.x * 32, oy0 = blockIdx.y * 32;
    int ix0 = ox0 * 2, iy0 = oy0 * 2;
    float acc[8][2][2];
#pragma unroll
    for (int g = 0; g < 8; g++)
#pragma unroll
        for (int a = 0; a < 2; a++)
#pragma unroll
            for (int c = 0; c < 2; c++) acc[g][a][c] = 0.f;
    for (int ci = 0; ci < 64; ci++) {
        __syncthreads();
        const float* inp = in + (size_t)(b * 64 + ci) * Hin * Hin;
        for (int i = tid; i < 65 * 65; i += 256) {
            int r = iy0 + i / 65, c = ix0 + i % 65;
            sx[i] = (r < Hin && c < Hin) ? inp[(size_t)r * Hin + c] : 0.f;
        }
        __syncthreads();
        float xr[5][5];
        int rb = threadIdx.y * 4, cb = threadIdx.x * 4;
#pragma unroll
        for (int a = 0; a < 5; a++)
#pragma unroll
            for (int c = 0; c < 5; c++) xr[a][c] = sx[(rb + a) * 65 + cb + c];
        const float* wbase = &sw[ci * 72];
#pragma unroll
        for (int t = 0; t < 9; t++) {
            int ky = t / 3, kx = t % 3;
            float4 wa = *reinterpret_cast<const float4*>(wbase + t * 8);
            float4 wb = *reinterpret_cast<const float4*>(wbase + t * 8 + 4);
            float w8[8] = {wa.x, wa.y, wa.z, wa.w, wb.x, wb.y, wb.z, wb.w};
#pragma unroll
            for (int g = 0; g < 8; g++)
#pragma unroll
                for (int py = 0; py < 2; py++)
#pragma unroll
                    for (int px = 0; px < 2; px++)
                        acc[g][py][px] += xr[py * 2 + ky][px * 2 + kx] * w8[g];
        }
    }
#pragma unroll
    for (int g = 0; g < 8; g++) {
        int co = co0 + g;
        float sB = beta[co];
#pragma unroll
        for (int py = 0; py < 2; py++)
#pragma unroll
            for (int px = 0; px < 2; px++) {
                int oy = oy0 + threadIdx.y * 2 + py, ox = ox0 + threadIdx.x * 2 + px;
                if (oy < Hout && ox < Hout) {
                    float v = fmaxf(acc[g][py][px] + sB, 0.f);
                    out[(size_t)(b * 64 + co) * Hout * Hout + (size_t)oy * Hout + ox] = v;
                }
            }
    }
}

// ---------- 1x1 conv, 8 co/block, 4 contiguous px/thread, f32x2 ----------
__global__ void conv1x1_k(const float* __restrict__ in, const float* __restrict__ wt,
                          const float* __restrict__ gamma, const float* __restrict__ beta,
                          float* __restrict__ out,
                          int CoutW, int Cout_buf, int npix, int useBN) {
    __shared__ float swt[8 * 64];
    int ng = CoutW >> 3;
    int b = blockIdx.z / ng;
    int co0 = (blockIdx.z % ng) << 3;
    int tid = threadIdx.x;
    for (int i = tid; i < 512; i += 256) swt[i] = wt[co0 * 64 + i];
    __syncthreads();
    int base = blockIdx.x * 1024 + tid * 4;
    const float* inb = in + (size_t)b * 64 * npix + base;
    ull acc2[8][2];
#pragma unroll
    for (int c = 0; c < 8; c++) { acc2[c][0] = 0ULL; acc2[c][1] = 0ULL; }
    for (int ci = 0; ci < 64; ci++) {
        float4 x = *reinterpret_cast<const float4*>(inb + (size_t)ci * npix);
        ull xp0 = pk2(x.x, x.y), xp1 = pk2(x.z, x.w);
#pragma unroll
        for (int c = 0; c < 8; c++) {
            float w = swt[c * 64 + ci];
            ull wd = pk2(w, w);
            acc2[c][0] = fma2(xp0, wd, acc2[c][0]);
            acc2[c][1] = fma2(xp1, wd, acc2[c][1]);
        }
    }
#pragma unroll
    for (int c = 0; c < 8; c++) {
        int co = co0 + c;
        float sA = 1.f, sB = 0.f;
        if (useBN) { sA = gamma[co] * BN_SC; sB = beta[co]; }
        else if (beta) sB = beta[co];
        float a0, a1, a2, a3;
        upk2(acc2[c][0], a0, a1);
        upk2(acc2[c][1], a2, a3);
        float4 o;
        o.x = a0 * sA + sB; o.y = a1 * sA + sB;
        o.z = a2 * sA + sB; o.w = a3 * sA + sB;
        *reinterpret_cast<float4*>(out + (size_t)(b * Cout_buf + co) * npix + base) = o;
    }
}

// ---------- 1x1 conv + bias + log_softmax ----------
__global__ void conv1x1_lsm_k(const float* __restrict__ in, const float* __restrict__ wt,
                              const float* __restrict__ bias, float* __restrict__ out) {
    __shared__ float swt[4096];
    __shared__ float sb[64];
    int tid = threadIdx.x;
    for (int i = tid; i < 4096; i += 256) swt[i] = wt[i];
    if (tid < 64) sb[tid] = bias[tid];
    __syncthreads();
    int p = blockIdx.x * 256 + tid;
    int b = blockIdx.z;
    const float* inb = in + (size_t)b * 64 * HW;
    float acc[64];
#pragma unroll
    for (int c = 0; c < 64; c++) acc[c] = sb[c];
    for (int ci = 0; ci < 64; ci++) {
        float xv = inb[(size_t)ci * HW + p];
#pragma unroll
        for (int c = 0; c < 64; c++) acc[c] += swt[c * 64 + ci] * xv;
    }
    float m = -1e30f;
#pragma unroll
    for (int c = 0; c < 64; c++) m = fmaxf(m, acc[c]);
    float s = 0.f;
#pragma unroll
    for (int c = 0; c < 64; c++) s += __expf(acc[c] - m);
    float l = m + __logf(s);
#pragma unroll
    for (int c = 0; c < 64; c++) out[(size_t)(b * 64 + c) * HW + p] = acc[c] - l;
}

// ---------- forward row DFT, real -> half spectrum (t=0..63) ----------
__global__ void dftf_rows_k(const float* __restrict__ x, float* __restrict__ Are,
                            float* __restrict__ Aim) {
    __shared__ float sx[8 * H2];
    size_t row0 = (size_t)blockIdx.x * 8;
    int t = threadIdx.x;
    const float* xp = x + row0 * H2;
    for (int i = t; i < 8 * H2; i += 64) sx[i] = xp[i];
    __syncthreads();
    float ar[8], ai[8];
#pragma unroll
    for (int r = 0; r < 8; r++) { ar[r] = 0.f; ai[r] = 0.f; }
    for (int n = 0; n < H2; n++) {
        float wr = g_Wre[n * H2 + t], wi = g_Wim[n * H2 + t];
#pragma unroll
        for (int r = 0; r < 8; r++) {
            float xv = sx[r * H2 + n];
            ar[r] += xv * wr; ai[r] += xv * wi;
        }
    }
#pragma unroll
    for (int r = 0; r < 8; r++) {
        Are[(row0 + r) * 64 + t] = ar[r];
        Aim[(row0 + r) * 64 + t] = ai[r];
    }
}

// ---------- column DFT, 16 k/block (R8-proven); optional fused mask ----------
__global__ void dftc_k(const float* __restrict__ Xre, const float* __restrict__ Xim,
                       float* __restrict__ Ore, float* __restrict__ Oim,
                       float wisign, float scale, int domask) {
    __shared__ float swr[16 * H2], swi[16 * H2];
    int img = blockIdx.x;
    int k0 = blockIdx.y * 16;
    int nk = min(16, H2 - k0);
    int t = threadIdx.x;
    for (int i = t; i < 16 * H2; i += 64) {
        int kk = i / H2, h = i % H2;
        bool ok = (k0 + kk) < H2;
        swr[i] = ok ? g_Wre[(k0 + kk) * H2 + h] : 0.f;
        swi[i] = ok ? wisign * g_Wim[(k0 + kk) * H2 + h] : 0.f;
    }
    __syncthreads();
    const float* xr = Xre + (size_t)img * NH2;
    const float* xi = Xim + (size_t)img * NH2;
    int c2 = t - (t >= 63 ? 126 : 0);
    int c2sq = c2 * c2;
    float or_[16], oi_[16];
#pragma unroll
    for (int i = 0; i < 16; i++) { or_[i] = 0.f; oi_[i] = 0.f; }
    for (int h = 0; h < H2; h++) {
        float a = xr[h * 64 + t], bb = xi[h * 64 + t];
        if (domask) {
            int c1 = h - (h >= 63 ? 126 : 0);
            float f = (c1 * c1 + c2sq > 1600) ? sqrtf(a * a + bb * bb) : 0.f;
            a *= f; bb *= f;
        }
#pragma unroll
        for (int i = 0; i < 16; i++) {
            float wr = swr[i * H2 + h], wi = swi[i * H2 + h];
            or_[i] += a * wr - bb * wi;
            oi_[i] += a * wi + bb * wr;
        }
    }
    float* pr = Ore + (size_t)img * NH2;
    float* pi = Oim + (size_t)img * NH2;
    for (int i = 0; i < nk; i++) {
        pr[(k0 + i) * 64 + t] = or_[i] * scale;
        pi[(k0 + i) * 64 + t] = oi_[i] * scale;
    }
}

// ---------- inverse row DFT via conjugate symmetry -> |real| -> blend ----------
__global__ void dfti_rows_mag_k(const float* __restrict__ Cre, const float* __restrict__ Cim,
                                const float* __restrict__ gbw, float* __restrict__ xc) {
    __shared__ float sre[8 * 64], sim[8 * 64];
    size_t row0 = (size_t)blockIdx.x * 8;
    int t = threadIdx.x;
    const float* pr = Cre + row0 * 64;
    const float* pi = Cim + row0 * 64;
    for (int i = t; i < 512; i += 128) { sre[i] = pr[i]; sim[i] = pi[i]; }
    __syncthreads();
    if (t >= H2) return;
    float acc[8];
#pragma unroll
    for (int r = 0; r < 8; r++) acc[r] = 0.f;
    for (int t2 = 1; t2 < 63; t2++) {
        float wr = g_Wre[t2 * H2 + t], wi = g_Wim[t2 * H2 + t];
#pragma unroll
        for (int r = 0; r < 8; r++)
            acc[r] += sre[r * 64 + t2] * wr + sim[r * 64 + t2] * wi;
    }
    float sgn = (t & 1) ? -1.f : 1.f;
    float wa = fmaxf(gbw[0], 0.f), wb = fmaxf(gbw[1], 0.f);
    float s = wa + wb + 1e-8f;
    float f0 = wa / s, f1 = wb / s;
#pragma unroll
    for (int r = 0; r < 8; r++) {
        float val = 2.f * acc[r] + sre[r * 64] + sgn * sre[r * 64 + 63];
        size_t idx = (row0 + r) * H2 + t;
        float mag = fabsf(val) * (1.f / 126.f);
        xc[idx] = f0 * mag + f1 * xc[idx];
    }
}

__global__ void maxpool_k(const float* __restrict__ in, float* __restrict__ out,
                          int Hin, int Hout, int stride, int total) {
    int idx = blockIdx.x * blockDim.x + threadIdx.x;
    if (idx >= total) return;
    int plane = idx / (Hout * Hout);
    int rc = idx % (Hout * Hout);
    int r = (rc / Hout) * stride, c = (rc % Hout) * stride;
    const float* p = in + (size_t)plane * Hin * Hin;
    out[idx] = fmaxf(fmaxf(p[r * Hin + c], p[r * Hin + c + 1]),
                     fmaxf(p[(r + 1) * Hin + c], p[(r + 1) * Hin + c + 1]));
}

__global__ void resize_k(const float* __restrict__ in, float* __restrict__ out) {
    int idx = blockIdx.x * blockDim.x + threadIdx.x;
    if (idx >= NPIX) return;
    int plane = idx >> 14;
    int ij = idx & 16383;
    int i = ij >> 7, j = ij & 127;
    const float* p = in + (size_t)plane * 961;
    const float sc = 31.f / 128.f;
    float fy = (i + 0.5f) * sc - 0.5f;
    int y0 = (int)floorf(fy);
    float wy = fy - (float)y0;
    int ya = min(max(y0, 0), 30), yb = min(max(y0 + 1, 0), 30);
    float fx = (j + 0.5f) * sc - 0.5f;
    int x0 = (int)floorf(fx);
    float wx = fx - (float)x0;
    int xa = min(max(x0, 0), 30), xb = min(max(x0 + 1, 0), 30);
    out[idx] = (1.f - wy) * ((1.f - wx) * p[ya * 31 + xa] + wx * p[ya * 31 + xb]) +
               wy * ((1.f - wx) * p[yb * 31 + xa] + wx * p[yb * 31 + xb]);
}

__global__ void attn_k(const float* __restrict__ qkv, float* __restrict__ o) {
    __shared__ float sk[64 * 8], sv[64 * 8];
    int win = blockIdx.x, head = blockIdx.y, b = blockIdx.z;
    int gi = win >> 4, gj = win & 15;
    int t = threadIdx.x;
    int wi = t >> 3, wj = t & 7;
    int pix = ((gi * 8 + wi) << 7) + gj * 8 + wj;
    size_t base = (size_t)b * 192 * HW;
    float q[8];
#pragma unroll
    for (int d = 0; d < 8; d++) {
        int ch = head * 8 + d;
        q[d] = qkv[base + (size_t)ch * HW + pix] * ATT_SCALE;
        sk[t * 8 + d] = qkv[base + (size_t)(64 + ch) * HW + pix];
        sv[t * 8 + d] = qkv[base + (size_t)(128 + ch) * HW + pix];
    }
    __syncthreads();
    const float* rp = g_rpb + (head * 64 + t) * 64;
    float dots[64];
    float m = -1e30f;
    for (int j = 0; j < 64; j++) {
        float s = rp[j];
#pragma unroll
        for (int d = 0; d < 8; d++) s += q[d] * sk[j * 8 + d];
        dots[j] = s;
        m = fmaxf(m, s);
    }
    float sum = 0.f;
    for (int j = 0; j < 64; j++) { dots[j] = __expf(dots[j] - m); sum += dots[j]; }
    float inv = 1.f / sum;
    float acc[8];
#pragma unroll
    for (int d = 0; d < 8; d++) acc[d] = 0.f;
    for (int j = 0; j < 64; j++) {
        float a = dots[j] * inv;
#pragma unroll
        for (int d = 0; d < 8; d++) acc[d] += a * sv[j * 8 + d];
    }
#pragma unroll
    for (int d = 0; d < 8; d++)
        o[(size_t)(b * 64 + head * 8 + d) * HW + pix] = acc[d];
}

__global__ void pooladd_k(const float* __restrict__ o, const float* __restrict__ loc,
                          float* __restrict__ out) {
    int idx = blockIdx.x * blockDim.x + threadIdx.x;
    if (idx >= NPIX) return;
    int plane = idx >> 14;
    int ij = idx & 16383;
    int i = ij >> 7, j = ij & 127;
    const float* p = o + (size_t)plane * HW;
    float sx = 0.f, sy = 0.f;
#pragma unroll
    for (int d = -3; d <= 4; d++) {
        int r = i + d;
        if (r >= 0 && r <= 128) sx += p[(r == 128 ? 126 : r) * 128 + j];
        int c = j + d;
        if (c >= 0 && c <= 128) sy += p[i * 128 + (c == 128 ? 126 : c)];
    }
    out[idx] = sx * 0.125f + sy * 0.125f + loc[idx];
}

__global__ void dwconv_k(const float* __restrict__ in, const float* __restrict__ wdw,
                         const float* __restrict__ g, const float* __restrict__ bb,
                         float* __restrict__ out) {
    __shared__ float sx[23 * 23];
    __shared__ float sw[64];
    int c = blockIdx.z & 63, b = blockIdx.z >> 6;
    int tid = threadIdx.y * 16 + threadIdx.x;
    if (tid < 64) sw[tid] = wdw[c * 64 + tid];
    const float* p = in + (size_t)(b * 64 + c) * HW;
    int iy0 = blockIdx.y * 16 - 3, ix0 = blockIdx.x * 16 - 3;
    for (int i = tid; i < 529; i += 256) {
        int r = iy0 + i / 23, cc = ix0 + i % 23;
        sx[i] = (r >= 0 && r < 128 && cc >= 0 && cc < 128) ? p[r * 128 + cc] : 0.f;
    }
    __syncthreads();
    float acc = 0.f;
#pragma unroll
    for (int ky = 0; ky < 8; ky++)
#pragma unroll
        for (int kx = 0; kx < 8; kx++)
            acc += sx[(threadIdx.y + ky) * 23 + threadIdx.x + kx] * sw[ky * 8 + kx];
    int oy = blockIdx.y * 16 + threadIdx.y, ox = blockIdx.x * 16 + threadIdx.x;
    out[(size_t)(b * 64 + c) * HW + oy * 128 + ox] = acc * (g[c] * BN_SC) + bb[c];
}

extern "C" void kernel_launch(void* const* d_in, const int* in_sizes, int n_in,
                              void* d_out, int out_size) {
    const float* x = (const float*)d_in[0];
    const float* w_qkv = (const float*)d_in[1];
    const float* w_l1 = (const float*)d_in[2];
    const float* g_l1 = (const float*)d_in[3];
    const float* b_l1 = (const float*)d_in[4];
    const float* w_l2 = (const float*)d_in[5];
    const float* g_l2 = (const float*)d_in[6];
    const float* b_l2 = (const float*)d_in[7];
    const float* f_cos = (const float*)d_in[8];
    const float* f_sin = (const float*)d_in[9];
    const float* gb_b1 = (const float*)d_in[10];
    const float* gb_b2 = (const float*)d_in[11];
    const float* gb_w = (const float*)d_in[12];
    const float* w_post = (const float*)d_in[13];
    const float* g_post = (const float*)d_in[14];
    const float* b_post = (const float*)d_in[15];
    const float* w_gc = (const float*)d_in[16];
    const float* b_gc = (const float*)d_in[17];
    const float* w_gc1 = (const float*)d_in[18];
    const float* b_gc1 = (const float*)d_in[19];
    const float* w_gc2 = (const float*)d_in[20];
    const float* b_gc2 = (const float*)d_in[21];
    const float* rpb_table = (const float*)d_in[22];
    const float* w_dw = (const float*)d_in[23];
    const float* g_proj = (const float*)d_in[24];
    const float* b_proj = (const float*)d_in[25];
    const float* w_pw = (const float*)d_in[26];
    const int* rel_index = (const int*)d_in[27];

    float *buf1, *buf2, *buf3, *qkvb, *xc, *Are, *Aim, *Bre, *Bim, *wpack, *bpack;
    cudaGetSymbolAddress((void**)&buf1, g_buf1);
    cudaGetSymbolAddress((void**)&buf2, g_buf2);
    cudaGetSymbolAddress((void**)&buf3, g_buf3);
    cudaGetSymbolAddress((void**)&qkvb, g_qkv);
    cudaGetSymbolAddress((void**)&xc, g_xc);
    cudaGetSymbolAddress((void**)&Are, g_Are);
    cudaGetSymbolAddress((void**)&Aim, g_Aim);
    cudaGetSymbolAddress((void**)&Bre, g_Bre);
    cudaGetSymbolAddress((void**)&Bim, g_Bim);
    cudaGetSymbolAddress((void**)&wpack, g_wpack);
    cudaGetSymbolAddress((void**)&bpack, g_bpack);

    dim3 thr2(16, 16);
    init_w126_k<<<(HW126 + 255) / 256, 256>>>();
    init_rpb_k<<<128, 256>>>(rpb_table, rel_index);
    pack_gabor_k<<<72, 256>>>(f_cos, f_sin, gb_b1, gb_b2);

    // local = bn(conv1x1) + bn(conv3x3)
    conv1x1_k<<<dim3(16, 1, 64), 256>>>(x, w_l2, g_l2, b_l2, buf1, 64, 64, HW, 1);
    conv3x3s1_k<<<dim3(2, 4, 64), thr2>>>(x, w_l1, g_l1, b_l1, buf1, buf1,
                                          64, 64, 128, 128, 128, 128, 1, 0, 1);
    // fused gabor convs (valid, 126x126)
    conv3x3s1_k<<<dim3(2, 4, 64), thr2>>>(buf1, wpack, nullptr, bpack, nullptr, xc,
                                          64, 64, 128, 128, 126, 126, 0, 0, 0);
    // FFT high-pass (half spectrum, mask fused into inverse col pass)
    dftf_rows_k<<<8064, 64>>>(xc, Are, Aim);
    dftc_k<<<dim3(512, 8), 64>>>(Are, Aim, Bre, Bim, 1.f, 1.f, 0);
    dftc_k<<<dim3(512, 8), 64>>>(Bre, Bim, Are, Aim, -1.f, 1.f / 126.f, 1);
    dfti_rows_mag_k<<<8064, 128>>>(Are, Aim, gb_w, xc);
    // post conv + relu6
    conv3x3s1_k<<<dim3(2, 4, 64), thr2>>>(xc, w_post, g_post, b_post, nullptr, Are,
                                          64, 64, 126, 126, 126, 126, 1, 2, 1);
    maxpool_k<<<(8000000 + 255) / 256, 256>>>(Are, Bre, 126, 125, 1, 8000000);
    conv3x3s2_k<<<dim3(2, 2, 64), thr2>>>(Bre, w_gc, b_gc, Aim, 125, 62);
    maxpool_k<<<(492032 + 255) / 256, 256>>>(Aim, Bim, 62, 31, 2, 492032);
    resize_k<<<NPIX / 256, 256>>>(Bim, buf2);
    conv3x3s1_k<<<dim3(2, 4, 64), thr2>>>(buf2, w_gc1, nullptr, b_gc1, nullptr, buf3,
                                          64, 64, 128, 128, 128, 128, 1, 1, 0);
    conv1x1_lsm_k<<<dim3(64, 1, 8), 256>>>(buf3, w_gc2, b_gc2, buf1);
    // global branch
    conv1x1_k<<<dim3(16, 1, 192), 256>>>(x, w_qkv, nullptr, nullptr, qkvb, 192, 192, HW, 0);
    attn_k<<<dim3(256, 8, 8), 64>>>(qkvb, buf2);
    pooladd_k<<<NPIX / 256, 256>>>(buf2, buf1, buf3);
    // projection
    dwconv_k<<<dim3(8, 8, 512), thr2>>>(buf3, w_dw, g_proj, b_proj, buf2);
    conv1x1_k<<<dim3(16, 1, 64), 256>>>(buf2, w_pw, nullptr, nullptr, (float*)d_out,
                                        64, 64, HW, 0);
}

// round 16
// speedup vs baseline: 1.2616x; 1.2616x over previous
#include <cuda_runtime.h>
#include <math.h>

#define HW 16384
#define NPIX 8388608
#define H2 126
#define HW126 15876
#define N2 8128512        // 512*126*126
#define NH2 8064          // 126*64 half-spectrum per image
#define NHALF 4128768     // 512*8064
#define BN_SC 0.9999950000374997f
#define ATT_SCALE 0.35355339059327373f

typedef unsigned long long ull;

__device__ __forceinline__ ull pk2(float lo, float hi) {
    ull r; asm("mov.b64 %0, {%1, %2};" : "=l"(r) : "f"(lo), "f"(hi)); return r;
}
__device__ __forceinline__ void upk2(ull v, float& lo, float& hi) {
    asm("mov.b64 {%0, %1}, %2;" : "=f"(lo), "=f"(hi) : "l"(v));
}
__device__ __forceinline__ ull fma2(ull a, ull b, ull c) {
    ull d; asm("fma.rn.f32x2 %0, %1, %2, %3;" : "=l"(d) : "l"(a), "l"(b), "l"(c)); return d;
}

__device__ float g_buf1[NPIX];
__device__ float g_buf2[NPIX];
__device__ float g_buf3[NPIX];
__device__ float g_qkv[3 * NPIX];
__device__ float g_xc[N2];
__device__ float g_Are[N2];   // reused as post-conv output (needs N2)
__device__ float g_Aim[NHALF];
__device__ float g_Bre[N2];   // reused as maxpool output (needs 8000000)
__device__ float g_Bim[NHALF];
__device__ float g_Wre[HW126];
__device__ float g_Wim[HW126];
__device__ float g_rpb[8 * 64 * 64];
__device__ float g_wpack[64 * 576];
__device__ float g_bpack[64];

__global__ void init_w126_k() {
    int i = blockIdx.x * blockDim.x + threadIdx.x;
    if (i >= HW126) return;
    int k = i / H2, n = i % H2;
    int t = (k * n) % H2;
    float s, c;
    sincospif(-2.0f * (float)t / 126.0f, &s, &c);
    g_Wre[i] = c; g_Wim[i] = s;
}

__global__ void init_rpb_k(const float* __restrict__ table, const int* __restrict__ relidx) {
    int i = blockIdx.x * blockDim.x + threadIdx.x;
    if (i >= 8 * 4096) return;
    int h = i / 4096, ij = i % 4096;
    g_rpb[i] = table[relidx[ij] * 8 + h];
}

__global__ void pack_gabor_k(const float* __restrict__ fc, const float* __restrict__ fs,
                             const float* __restrict__ b1, const float* __restrict__ b2) {
    int i = blockIdx.x * 256 + threadIdx.x;
    if (i < 32 * 576) { g_wpack[i] = fc[i]; g_wpack[18432 + i] = fs[i]; }
    if (i < 32) { g_bpack[i] = b1[i]; g_bpack[32 + i] = b2[i]; }
}

// ---------- 3x3 conv stride 1: 64x32 out tile, 8 co x (2x4) px per thread ----------
// smem weights transposed to [ci][tap][g] so each tap reads 8 co-weights via 2x LDS.128
#define TW 68            // smem row stride (16B aligned, 34 rows)
__global__ void __launch_bounds__(256, 2)
conv3x3s1_k(const float* __restrict__ in, const float* __restrict__ wt,
            const float* __restrict__ gamma, const float* __restrict__ beta,
            const float* __restrict__ prev, float* __restrict__ out,
            int CoutW, int Cout_buf, int Hin, int Win, int Hout, int Wout,
            int pad, int act, int useBN) {
    __shared__ __align__(16) float sx[2][34 * TW];
    __shared__ __align__(16) float sw[64 * 9 * 8];   // [ci][tap][g]
    int ng = CoutW >> 3;
    int b = blockIdx.z / ng;
    int co0 = (blockIdx.z % ng) << 3;
    int tx = threadIdx.x, ty = threadIdx.y;
    int tid = ty * 16 + tx;
    for (int i = tid; i < 8 * 64 * 9; i += 256) {
        int g = i / 576, r = i % 576;          // r = ci*9 + tap
        sw[r * 8 + g] = wt[co0 * 576 + i];
    }
    int ox0 = blockIdx.x * 64, oy0 = blockIdx.y * 32;
    int ix0 = ox0 - pad, iy0 = oy0 - pad;
    float acc[8][2][4];
#pragma unroll
    for (int g = 0; g < 8; g++)
#pragma unroll
        for (int a = 0; a < 2; a++)
#pragma unroll
            for (int c = 0; c < 4; c++) acc[g][a][c] = 0.f;
    const float* inp0 = in + (size_t)b * 64 * Hin * Win;
    for (int i = tid; i < 34 * TW; i += 256) {
        int rr = i / TW, cc = i % TW;
        int r = iy0 + rr, c = ix0 + cc;
        sx[0][i] = (cc < 66 && r >= 0 && r < Hin && c >= 0 && c < Win)
                       ? inp0[(size_t)r * Win + c] : 0.f;
    }
    __syncthreads();
    int rb = ty * 2, cb = tx * 4;
    for (int ci = 0; ci < 64; ci++) {
        int cur = ci & 1;
        if (ci < 63) {
            const float* inp = inp0 + (size_t)(ci + 1) * Hin * Win;
            for (int i = tid; i < 34 * TW; i += 256) {
                int rr = i / TW, cc = i % TW;
                int r = iy0 + rr, c = ix0 + cc;
                sx[cur ^ 1][i] = (cc < 66 && r >= 0 && r < Hin && c >= 0 && c < Win)
                                     ? inp[(size_t)r * Win + c] : 0.f;
            }
        }
        float xr[4][6];
#pragma unroll
        for (int a = 0; a < 4; a++) {
            const float* rowp = &sx[cur][(rb + a) * TW + cb];
            float4 v4 = *reinterpret_cast<const float4*>(rowp);
            float2 v2 = *reinterpret_cast<const float2*>(rowp + 4);
            xr[a][0] = v4.x; xr[a][1] = v4.y; xr[a][2] = v4.z; xr[a][3] = v4.w;
            xr[a][4] = v2.x; xr[a][5] = v2.y;
        }
        const float* wbase = &sw[ci * 72];
#pragma unroll
        for (int t = 0; t < 9; t++) {
            int ky = t / 3, kx = t % 3;
            float4 wa = *reinterpret_cast<const float4*>(wbase + t * 8);
            float4 wb = *reinterpret_cast<const float4*>(wbase + t * 8 + 4);
            float w8[8] = {wa.x, wa.y, wa.z, wa.w, wb.x, wb.y, wb.z, wb.w};
#pragma unroll
            for (int g = 0; g < 8; g++)
#pragma unroll
                for (int py = 0; py < 2; py++)
#pragma unroll
                    for (int px = 0; px < 4; px++)
                        acc[g][py][px] += xr[py + ky][px + kx] * w8[g];
        }
        __syncthreads();
    }
#pragma unroll
    for (int g = 0; g < 8; g++) {
        int co = co0 + g;
        float sA = 1.f, sB = 0.f;
        if (useBN) { sA = gamma[co] * BN_SC; sB = beta[co]; }
        else if (beta) sB = beta[co];
#pragma unroll
        for (int py = 0; py < 2; py++)
#pragma unroll
            for (int px = 0; px < 4; px++) {
                int oy = oy0 + rb + py, ox = ox0 + cb + px;
                if (oy < Hout && ox < Wout) {
                    float v = acc[g][py][px] * sA + sB;
                    if (act == 1) v = fmaxf(v, 0.f);
                    else if (act == 2) v = fminf(fmaxf(v, 0.f), 6.f);
                    size_t oi = (size_t)(b * Cout_buf + co) * Hout * Wout +
                                (size_t)oy * Wout + ox;
                    if (prev) v += prev[oi];
                    out[oi] = v;
                }
            }
    }
}

// ---------- 3x3 conv stride 2 (w_gc), 8 co/block, transposed weights ----------
__global__ void __launch_bounds__(256, 2)
conv3x3s2_k(const float* __restrict__ in, const float* __restrict__ wt,
            const float* __restrict__ beta, float* __restrict__ out,
            int Hin, int Hout) {
    __shared__ __align__(16) float sw[64 * 9 * 8];   // [ci][tap][g]  (declared first: 16B base)
    __shared__ __align__(16) float sx[65 * 65 + 3];  // padded to keep others aligned
    int b = blockIdx.z >> 3;
    int co0 = (blockIdx.z & 7) << 3;
    int tid = threadIdx.y * 16 + threadIdx.x;
    for (int i = tid; i < 8 * 64 * 9; i += 256) {
        int g = i / 576, r = i % 576;
        sw[r * 8 + g] = wt[co0 * 576 + i];
    }
    int ox0 = blockIdx.x * 32, oy0 = blockIdx.y * 32;
    int ix0 = ox0 * 2, iy0 = oy0 * 2;
    float acc[8][2][2];
#pragma unroll
    for (int g = 0; g < 8; g++)
#pragma unroll
        for (int a = 0; a < 2; a++)
#pragma unroll
            for (int c = 0; c < 2; c++) acc[g][a][c] = 0.f;
    for (int ci = 0; ci < 64; ci++) {
        __syncthreads();
        const float* inp = in + (size_t)(b * 64 + ci) * Hin * Hin;
        for (int i = tid; i < 65 * 65; i += 256) {
            int r = iy0 + i / 65, c = ix0 + i % 65;
            sx[i] = (r < Hin && c < Hin) ? inp[(size_t)r * Hin + c] : 0.f;
        }
        __syncthreads();
        float xr[5][5];
        int rb = threadIdx.y * 4, cb = threadIdx.x * 4;
#pragma unroll
        for (int a = 0; a < 5; a++)
#pragma unroll
            for (int c = 0; c < 5; c++) xr[a][c] = sx[(rb + a) * 65 + cb + c];
        const float* wbase = &sw[ci * 72];
#pragma unroll
        for (int t = 0; t < 9; t++) {
            int ky = t / 3, kx = t % 3;
            float4 wa = *reinterpret_cast<const float4*>(wbase + t * 8);
            float4 wb = *reinterpret_cast<const float4*>(wbase + t * 8 + 4);
            float w8[8] = {wa.x, wa.y, wa.z, wa.w, wb.x, wb.y, wb.z, wb.w};
#pragma unroll
            for (int g = 0; g < 8; g++)
#pragma unroll
                for (int py = 0; py < 2; py++)
#pragma unroll
                    for (int px = 0; px < 2; px++)
                        acc[g][py][px] += xr[py * 2 + ky][px * 2 + kx] * w8[g];
        }
    }
#pragma unroll
    for (int g = 0; g < 8; g++) {
        int co = co0 + g;
        float sB = beta[co];
#pragma unroll
        for (int py = 0; py < 2; py++)
#pragma unroll
            for (int px = 0; px < 2; px++) {
                int oy = oy0 + threadIdx.y * 2 + py, ox = ox0 + threadIdx.x * 2 + px;
                if (oy < Hout && ox < Hout) {
                    float v = fmaxf(acc[g][py][px] + sB, 0.f);
                    out[(size_t)(b * 64 + co) * Hout * Hout + (size_t)oy * Hout + ox] = v;
                }
            }
    }
}

// ---------- 1x1 conv, 8 co/block, 4 contiguous px/thread, f32x2 ----------
__global__ void conv1x1_k(const float* __restrict__ in, const float* __restrict__ wt,
                          const float* __restrict__ gamma, const float* __restrict__ beta,
                          float* __restrict__ out,
                          int CoutW, int Cout_buf, int npix, int useBN) {
    __shared__ float swt[8 * 64];
    int ng = CoutW >> 3;
    int b = blockIdx.z / ng;
    int co0 = (blockIdx.z % ng) << 3;
    int tid = threadIdx.x;
    for (int i = tid; i < 512; i += 256) swt[i] = wt[co0 * 64 + i];
    __syncthreads();
    int base = blockIdx.x * 1024 + tid * 4;
    const float* inb = in + (size_t)b * 64 * npix + base;
    ull acc2[8][2];
#pragma unroll
    for (int c = 0; c < 8; c++) { acc2[c][0] = 0ULL; acc2[c][1] = 0ULL; }
    for (int ci = 0; ci < 64; ci++) {
        float4 x = *reinterpret_cast<const float4*>(inb + (size_t)ci * npix);
        ull xp0 = pk2(x.x, x.y), xp1 = pk2(x.z, x.w);
#pragma unroll
        for (int c = 0; c < 8; c++) {
            float w = swt[c * 64 + ci];
            ull wd = pk2(w, w);
            acc2[c][0] = fma2(xp0, wd, acc2[c][0]);
            acc2[c][1] = fma2(xp1, wd, acc2[c][1]);
        }
    }
#pragma unroll
    for (int c = 0; c < 8; c++) {
        int co = co0 + c;
        float sA = 1.f, sB = 0.f;
        if (useBN) { sA = gamma[co] * BN_SC; sB = beta[co]; }
        else if (beta) sB = beta[co];
        float a0, a1, a2, a3;
        upk2(acc2[c][0], a0, a1);
        upk2(acc2[c][1], a2, a3);
        float4 o;
        o.x = a0 * sA + sB; o.y = a1 * sA + sB;
        o.z = a2 * sA + sB; o.w = a3 * sA + sB;
        *reinterpret_cast<float4*>(out + (size_t)(b * Cout_buf + co) * npix + base) = o;
    }
}

// ---------- 1x1 conv + bias + log_softmax ----------
__global__ void conv1x1_lsm_k(const float* __restrict__ in, const float* __restrict__ wt,
                              const float* __restrict__ bias, float* __restrict__ out) {
    __shared__ float swt[4096];
    __shared__ float sb[64];
    int tid = threadIdx.x;
    for (int i = tid; i < 4096; i += 256) swt[i] = wt[i];
    if (tid < 64) sb[tid] = bias[tid];
    __syncthreads();
    int p = blockIdx.x * 256 + tid;
    int b = blockIdx.z;
    const float* inb = in + (size_t)b * 64 * HW;
    float acc[64];
#pragma unroll
    for (int c = 0; c < 64; c++) acc[c] = sb[c];
    for (int ci = 0; ci < 64; ci++) {
        float xv = inb[(size_t)ci * HW + p];
#pragma unroll
        for (int c = 0; c < 64; c++) acc[c] += swt[c * 64 + ci] * xv;
    }
    float m = -1e30f;
#pragma unroll
    for (int c = 0; c < 64; c++) m = fmaxf(m, acc[c]);
    float s = 0.f;
#pragma unroll
    for (int c = 0; c < 64; c++) s += __expf(acc[c] - m);
    float l = m + __logf(s);
#pragma unroll
    for (int c = 0; c < 64; c++) out[(size_t)(b * 64 + c) * HW + p] = acc[c] - l;
}

// ---------- forward row DFT, real -> half spectrum (t=0..63) ----------
__global__ void dftf_rows_k(const float* __restrict__ x, float* __restrict__ Are,
                            float* __restrict__ Aim) {
    __shared__ float sx[8 * H2];
    size_t row0 = (size_t)blockIdx.x * 8;
    int t = threadIdx.x;
    const float* xp = x + row0 * H2;
    for (int i = t; i < 8 * H2; i += 64) sx[i] = xp[i];
    __syncthreads();
    float ar[8], ai[8];
#pragma unroll
    for (int r = 0; r < 8; r++) { ar[r] = 0.f; ai[r] = 0.f; }
    for (int n = 0; n < H2; n++) {
        float wr = g_Wre[n * H2 + t], wi = g_Wim[n * H2 + t];
#pragma unroll
        for (int r = 0; r < 8; r++) {
            float xv = sx[r * H2 + n];
            ar[r] += xv * wr; ai[r] += xv * wi;
        }
    }
#pragma unroll
    for (int r = 0; r < 8; r++) {
        Are[(row0 + r) * 64 + t] = ar[r];
        Aim[(row0 + r) * 64 + t] = ai[r];
    }
}

// ---------- column DFT, 16 k/block, h unrolled x2 with float2 twiddle LDS ----------
__global__ void dftc_k(const float* __restrict__ Xre, const float* __restrict__ Xim,
                       float* __restrict__ Ore, float* __restrict__ Oim,
                       float wisign, float scale, int domask) {
    __shared__ __align__(8) float swr[16 * H2], swi[16 * H2];
    int img = blockIdx.x;
    int k0 = blockIdx.y * 16;
    int nk = min(16, H2 - k0);
    int t = threadIdx.x;
    for (int i = t; i < 16 * H2; i += 64) {
        int kk = i / H2, h = i % H2;
        bool ok = (k0 + kk) < H2;
        swr[i] = ok ? g_Wre[(k0 + kk) * H2 + h] : 0.f;
        swi[i] = ok ? wisign * g_Wim[(k0 + kk) * H2 + h] : 0.f;
    }
    __syncthreads();
    const float* xr = Xre + (size_t)img * NH2;
    const float* xi = Xim + (size_t)img * NH2;
    int c2 = t - (t >= 63 ? 126 : 0);
    int c2sq = c2 * c2;
    float or_[16], oi_[16];
#pragma unroll
    for (int i = 0; i < 16; i++) { or_[i] = 0.f; oi_[i] = 0.f; }
    for (int h = 0; h < H2; h += 2) {
        float a0 = xr[h * 64 + t], b0 = xi[h * 64 + t];
        float a1 = xr[(h + 1) * 64 + t], b1 = xi[(h + 1) * 64 + t];
        if (domask) {
            int c1 = h - (h >= 63 ? 126 : 0);
            float f0m = (c1 * c1 + c2sq > 1600) ? sqrtf(a0 * a0 + b0 * b0) : 0.f;
            a0 *= f0m; b0 *= f0m;
            int c1b = (h + 1) - ((h + 1) >= 63 ? 126 : 0);
            float f1m = (c1b * c1b + c2sq > 1600) ? sqrtf(a1 * a1 + b1 * b1) : 0.f;
            a1 *= f1m; b1 *= f1m;
        }
#pragma unroll
        for (int i = 0; i < 16; i++) {
            float2 wr2 = *reinterpret_cast<const float2*>(&swr[i * H2 + h]);
            float2 wi2 = *reinterpret_cast<const float2*>(&swi[i * H2 + h]);
            or_[i] += a0 * wr2.x - b0 * wi2.x;
            oi_[i] += a0 * wi2.x + b0 * wr2.x;
            or_[i] += a1 * wr2.y - b1 * wi2.y;
            oi_[i] += a1 * wi2.y + b1 * wr2.y;
        }
    }
    float* pr = Ore + (size_t)img * NH2;
    float* pi = Oim + (size_t)img * NH2;
    for (int i = 0; i < nk; i++) {
        pr[(k0 + i) * 64 + t] = or_[i] * scale;
        pi[(k0 + i) * 64 + t] = oi_[i] * scale;
    }
}

// ---------- inverse row DFT via conjugate symmetry -> |real| -> blend ----------
__global__ void dfti_rows_mag_k(const float* __restrict__ Cre, const float* __restrict__ Cim,
                                const float* __restrict__ gbw, float* __restrict__ xc) {
    __shared__ float sre[8 * 64], sim[8 * 64];
    size_t row0 = (size_t)blockIdx.x * 8;
    int t = threadIdx.x;
    const float* pr = Cre + row0 * 64;
    const float* pi = Cim + row0 * 64;
    for (int i = t; i < 512; i += 128) { sre[i] = pr[i]; sim[i] = pi[i]; }
    __syncthreads();
    if (t >= H2) return;
    float acc[8];
#pragma unroll
    for (int r = 0; r < 8; r++) acc[r] = 0.f;
    for (int t2 = 1; t2 < 63; t2++) {
        float wr = g_Wre[t2 * H2 + t], wi = g_Wim[t2 * H2 + t];
#pragma unroll
        for (int r = 0; r < 8; r++)
            acc[r] += sre[r * 64 + t2] * wr + sim[r * 64 + t2] * wi;
    }
    float sgn = (t & 1) ? -1.f : 1.f;
    float wa = fmaxf(gbw[0], 0.f), wb = fmaxf(gbw[1], 0.f);
    float s = wa + wb + 1e-8f;
    float f0 = wa / s, f1 = wb / s;
#pragma unroll
    for (int r = 0; r < 8; r++) {
        float val = 2.f * acc[r] + sre[r * 64] + sgn * sre[r * 64 + 63];
        size_t idx = (row0 + r) * H2 + t;
        float mag = fabsf(val) * (1.f / 126.f);
        xc[idx] = f0 * mag + f1 * xc[idx];
    }
}

__global__ void maxpool_k(const float* __restrict__ in, float* __restrict__ out,
                          int Hin, int Hout, int stride, int total) {
    int idx = blockIdx.x * blockDim.x + threadIdx.x;
    if (idx >= total) return;
    int plane = idx / (Hout * Hout);
    int rc = idx % (Hout * Hout);
    int r = (rc / Hout) * stride, c = (rc % Hout) * stride;
    const float* p = in + (size_t)plane * Hin * Hin;
    out[idx] = fmaxf(fmaxf(p[r * Hin + c], p[r * Hin + c + 1]),
                     fmaxf(p[(r + 1) * Hin + c], p[(r + 1) * Hin + c + 1]));
}

__global__ void resize_k(const float* __restrict__ in, float* __restrict__ out) {
    int idx = blockIdx.x * blockDim.x + threadIdx.x;
    if (idx >= NPIX) return;
    int plane = idx >> 14;
    int ij = idx & 16383;
    int i = ij >> 7, j = ij & 127;
    const float* p = in + (size_t)plane * 961;
    const float sc = 31.f / 128.f;
    float fy = (i + 0.5f) * sc - 0.5f;
    int y0 = (int)floorf(fy);
    float wy = fy - (float)y0;
    int ya = min(max(y0, 0), 30), yb = min(max(y0 + 1, 0), 30);
    float fx = (j + 0.5f) * sc - 0.5f;
    int x0 = (int)floorf(fx);
    float wx = fx - (float)x0;
    int xa = min(max(x0, 0), 30), xb = min(max(x0 + 1, 0), 30);
    out[idx] = (1.f - wy) * ((1.f - wx) * p[ya * 31 + xa] + wx * p[ya * 31 + xb]) +
               wy * ((1.f - wx) * p[yb * 31 + xa] + wx * p[yb * 31 + xb]);
}

__global__ void attn_k(const float* __restrict__ qkv, float* __restrict__ o) {
    __shared__ float sk[64 * 8], sv[64 * 8];
    int win = blockIdx.x, head = blockIdx.y, b = blockIdx.z;
    int gi = win >> 4, gj = win & 15;
    int t = threadIdx.x;
    int wi = t >> 3, wj = t & 7;
    int pix = ((gi * 8 + wi) << 7) + gj * 8 + wj;
    size_t base = (size_t)b * 192 * HW;
    float q[8];
#pragma unroll
    for (int d = 0; d < 8; d++) {
        int ch = head * 8 + d;
        q[d] = qkv[base + (size_t)ch * HW + pix] * ATT_SCALE;
        sk[t * 8 + d] = qkv[base + (size_t)(64 + ch) * HW + pix];
        sv[t * 8 + d] = qkv[base + (size_t)(128 + ch) * HW + pix];
    }
    __syncthreads();
    const float* rp = g_rpb + (head * 64 + t) * 64;
    float dots[64];
    float m = -1e30f;
    for (int j = 0; j < 64; j++) {
        float s = rp[j];
#pragma unroll
        for (int d = 0; d < 8; d++) s += q[d] * sk[j * 8 + d];
        dots[j] = s;
        m = fmaxf(m, s);
    }
    float sum = 0.f;
    for (int j = 0; j < 64; j++) { dots[j] = __expf(dots[j] - m); sum += dots[j]; }
    float inv = 1.f / sum;
    float acc[8];
#pragma unroll
    for (int d = 0; d < 8; d++) acc[d] = 0.f;
    for (int j = 0; j < 64; j++) {
        float a = dots[j] * inv;
#pragma unroll
        for (int d = 0; d < 8; d++) acc[d] += a * sv[j * 8 + d];
    }
#pragma unroll
    for (int d = 0; d < 8; d++)
        o[(size_t)(b * 64 + head * 8 + d) * HW + pix] = acc[d];
}

__global__ void pooladd_k(const float* __restrict__ o, const float* __restrict__ loc,
                          float* __restrict__ out) {
    int idx = blockIdx.x * blockDim.x + threadIdx.x;
    if (idx >= NPIX) return;
    int plane = idx >> 14;
    int ij = idx & 16383;
    int i = ij >> 7, j = ij & 127;
    const float* p = o + (size_t)plane * HW;
    float sx = 0.f, sy = 0.f;
#pragma unroll
    for (int d = -3; d <= 4; d++) {
        int r = i + d;
        if (r >= 0 && r <= 128) sx += p[(r == 128 ? 126 : r) * 128 + j];
        int c = j + d;
        if (c >= 0 && c <= 128) sy += p[i * 128 + (c == 128 ? 126 : c)];
    }
    out[idx] = sx * 0.125f + sy * 0.125f + loc[idx];
}

__global__ void dwconv_k(const float* __restrict__ in, const float* __restrict__ wdw,
                         const float* __restrict__ g, const float* __restrict__ bb,
                         float* __restrict__ out) {
    __shared__ float sx[23 * 23];
    __shared__ float sw[64];
    int c = blockIdx.z & 63, b = blockIdx.z >> 6;
    int tid = threadIdx.y * 16 + threadIdx.x;
    if (tid < 64) sw[tid] = wdw[c * 64 + tid];
    const float* p = in + (size_t)(b * 64 + c) * HW;
    int iy0 = blockIdx.y * 16 - 3, ix0 = blockIdx.x * 16 - 3;
    for (int i = tid; i < 529; i += 256) {
        int r = iy0 + i / 23, cc = ix0 + i % 23;
        sx[i] = (r >= 0 && r < 128 && cc >= 0 && cc < 128) ? p[r * 128 + cc] : 0.f;
    }
    __syncthreads();
    float acc = 0.f;
#pragma unroll
    for (int ky = 0; ky < 8; ky++)
#pragma unroll
        for (int kx = 0; kx < 8; kx++)
            acc += sx[(threadIdx.y + ky) * 23 + threadIdx.x + kx] * sw[ky * 8 + kx];
    int oy = blockIdx.y * 16 + threadIdx.y, ox = blockIdx.x * 16 + threadIdx.x;
    out[(size_t)(b * 64 + c) * HW + oy * 128 + ox] = acc * (g[c] * BN_SC) + bb[c];
}

extern "C" void kernel_launch(void* const* d_in, const int* in_sizes, int n_in,
                              void* d_out, int out_size) {
    const float* x = (const float*)d_in[0];
    const float* w_qkv = (const float*)d_in[1];
    const float* w_l1 = (const float*)d_in[2];
    const float* g_l1 = (const float*)d_in[3];
    const float* b_l1 = (const float*)d_in[4];
    const float* w_l2 = (const float*)d_in[5];
    const float* g_l2 = (const float*)d_in[6];
    const float* b_l2 = (const float*)d_in[7];
    const float* f_cos = (const float*)d_in[8];
    const float* f_sin = (const float*)d_in[9];
    const float* gb_b1 = (const float*)d_in[10];
    const float* gb_b2 = (const float*)d_in[11];
    const float* gb_w = (const float*)d_in[12];
    const float* w_post = (const float*)d_in[13];
    const float* g_post = (const float*)d_in[14];
    const float* b_post = (const float*)d_in[15];
    const float* w_gc = (const float*)d_in[16];
    const float* b_gc = (const float*)d_in[17];
    const float* w_gc1 = (const float*)d_in[18];
    const float* b_gc1 = (const float*)d_in[19];
    const float* w_gc2 = (const float*)d_in[20];
    const float* b_gc2 = (const float*)d_in[21];
    const float* rpb_table = (const float*)d_in[22];
    const float* w_dw = (const float*)d_in[23];
    const float* g_proj = (const float*)d_in[24];
    const float* b_proj = (const float*)d_in[25];
    const float* w_pw = (const float*)d_in[26];
    const int* rel_index = (const int*)d_in[27];

    float *buf1, *buf2, *buf3, *qkvb, *xc, *Are, *Aim, *Bre, *Bim, *wpack, *bpack;
    cudaGetSymbolAddress((void**)&buf1, g_buf1);
    cudaGetSymbolAddress((void**)&buf2, g_buf2);
    cudaGetSymbolAddress((void**)&buf3, g_buf3);
    cudaGetSymbolAddress((void**)&qkvb, g_qkv);
    cudaGetSymbolAddress((void**)&xc, g_xc);
    cudaGetSymbolAddress((void**)&Are, g_Are);
    cudaGetSymbolAddress((void**)&Aim, g_Aim);
    cudaGetSymbolAddress((void**)&Bre, g_Bre);
    cudaGetSymbolAddress((void**)&Bim, g_Bim);
    cudaGetSymbolAddress((void**)&wpack, g_wpack);
    cudaGetSymbolAddress((void**)&bpack, g_bpack);

    dim3 thr2(16, 16);
    init_w126_k<<<(HW126 + 255) / 256, 256>>>();
    init_rpb_k<<<128, 256>>>(rpb_table, rel_index);
    pack_gabor_k<<<72, 256>>>(f_cos, f_sin, gb_b1, gb_b2);

    // local = bn(conv1x1) + bn(conv3x3)
    conv1x1_k<<<dim3(16, 1, 64), 256>>>(x, w_l2, g_l2, b_l2, buf1, 64, 64, HW, 1);
    conv3x3s1_k<<<dim3(2, 4, 64), thr2>>>(x, w_l1, g_l1, b_l1, buf1, buf1,
                                          64, 64, 128, 128, 128, 128, 1, 0, 1);
    // fused gabor convs (valid, 126x126)
    conv3x3s1_k<<<dim3(2, 4, 64), thr2>>>(buf1, wpack, nullptr, bpack, nullptr, xc,
                                          64, 64, 128, 128, 126, 126, 0, 0, 0);
    // FFT high-pass (half spectrum, mask fused into inverse col pass)
    dftf_rows_k<<<8064, 64>>>(xc, Are, Aim);
    dftc_k<<<dim3(512, 8), 64>>>(Are, Aim, Bre, Bim, 1.f, 1.f, 0);
    dftc_k<<<dim3(512, 8), 64>>>(Bre, Bim, Are, Aim, -1.f, 1.f / 126.f, 1);
    dfti_rows_mag_k<<<8064, 128>>>(Are, Aim, gb_w, xc);
    // post conv + relu6
    conv3x3s1_k<<<dim3(2, 4, 64), thr2>>>(xc, w_post, g_post, b_post, nullptr, Are,
                                          64, 64, 126, 126, 126, 126, 1, 2, 1);
    maxpool_k<<<(8000000 + 255) / 256, 256>>>(Are, Bre, 126, 125, 1, 8000000);
    conv3x3s2_k<<<dim3(2, 2, 64), thr2>>>(Bre, w_gc, b_gc, Aim, 125, 62);
    maxpool_k<<<(492032 + 255) / 256, 256>>>(Aim, Bim, 62, 31, 2, 492032);
    resize_k<<<NPIX / 256, 256>>>(Bim, buf2);
    conv3x3s1_k<<<dim3(2, 4, 64), thr2>>>(buf2, w_gc1, nullptr, b_gc1, nullptr, buf3,
                                          64, 64, 128, 128, 128, 128, 1, 1, 0);
    conv1x1_lsm_k<<<dim3(64, 1, 8), 256>>>(buf3, w_gc2, b_gc2, buf1);
    // global branch
    conv1x1_k<<<dim3(16, 1, 192), 256>>>(x, w_qkv, nullptr, nullptr, qkvb, 192, 192, HW, 0);
    attn_k<<<dim3(256, 8, 8), 64>>>(qkvb, buf2);
    pooladd_k<<<NPIX / 256, 256>>>(buf2, buf1, buf3);
    // projection
    dwconv_k<<<dim3(8, 8, 512), thr2>>>(buf3, w_dw, g_proj, b_proj, buf2);
    conv1x1_k<<<dim3(16, 1, 64), 256>>>(buf2, w_pw, nullptr, nullptr, (float*)d_out,
                                        64, 64, HW, 0);
}

// round 17
// speedup vs baseline: 1.2701x; 1.0068x over previous
#include <cuda_runtime.h>
#include <math.h>

#define HW 16384
#define NPIX 8388608
#define H2 126
#define HW126 15876
#define N2 8128512        // 512*126*126
#define NH2 8064          // 126*64 half-spectrum per image
#define NHALF 4128768     // 512*8064
#define BN_SC 0.9999950000374997f
#define ATT_SCALE 0.35355339059327373f

typedef unsigned long long ull;

__device__ __forceinline__ ull pk2(float lo, float hi) {
    ull r; asm("mov.b64 %0, {%1, %2};" : "=l"(r) : "f"(lo), "f"(hi)); return r;
}
__device__ __forceinline__ void upk2(ull v, float& lo, float& hi) {
    asm("mov.b64 {%0, %1}, %2;" : "=f"(lo), "=f"(hi) : "l"(v));
}
__device__ __forceinline__ ull fma2(ull a, ull b, ull c) {
    ull d; asm("fma.rn.f32x2 %0, %1, %2, %3;" : "=l"(d) : "l"(a), "l"(b), "l"(c)); return d;
}

__device__ float g_buf1[NPIX];
__device__ float g_buf2[NPIX];
__device__ float g_buf3[NPIX];
__device__ float g_qkv[3 * NPIX];
__device__ float g_xc[N2];
__device__ float g_Are[N2];   // reused as post-conv output (needs N2)
__device__ float g_Aim[NHALF];
__device__ float g_Bre[N2];   // reused as maxpool output (needs 8000000)
__device__ float g_Bim[NHALF];
__device__ float g_Wre[HW126];
__device__ float g_Wim[HW126];
__device__ float g_rpb[8 * 64 * 64];
__device__ float g_wpack[64 * 576];
__device__ float g_bpack[64];

__global__ void init_w126_k() {
    int i = blockIdx.x * blockDim.x + threadIdx.x;
    if (i >= HW126) return;
    int k = i / H2, n = i % H2;
    int t = (k * n) % H2;
    float s, c;
    sincospif(-2.0f * (float)t / 126.0f, &s, &c);
    g_Wre[i] = c; g_Wim[i] = s;
}

__global__ void init_rpb_k(const float* __restrict__ table, const int* __restrict__ relidx) {
    int i = blockIdx.x * blockDim.x + threadIdx.x;
    if (i >= 8 * 4096) return;
    int h = i / 4096, ij = i % 4096;
    g_rpb[i] = table[relidx[ij] * 8 + h];
}

__global__ void pack_gabor_k(const float* __restrict__ fc, const float* __restrict__ fs,
                             const float* __restrict__ b1, const float* __restrict__ b2) {
    int i = blockIdx.x * 256 + threadIdx.x;
    if (i < 32 * 576) { g_wpack[i] = fc[i]; g_wpack[18432 + i] = fs[i]; }
    if (i < 32) { g_bpack[i] = b1[i]; g_bpack[32 + i] = b2[i]; }
}

// ---------- 3x3 conv stride 1: 64x32 out tile, 8 co x (2x4) px per thread ----------
#define TW 68            // smem row stride (16B aligned, 34 rows)
__global__ void __launch_bounds__(256, 2)
conv3x3s1_k(const float* __restrict__ in, const float* __restrict__ wt,
            const float* __restrict__ gamma, const float* __restrict__ beta,
            const float* __restrict__ prev, float* __restrict__ out,
            int CoutW, int Cout_buf, int Hin, int Win, int Hout, int Wout,
            int pad, int act, int useBN) {
    __shared__ __align__(16) float sx[2][34 * TW];
    __shared__ __align__(16) float sw[64 * 9 * 8];   // [ci][tap][g]
    int ng = CoutW >> 3;
    int b = blockIdx.z / ng;
    int co0 = (blockIdx.z % ng) << 3;
    int tx = threadIdx.x, ty = threadIdx.y;
    int tid = ty * 16 + tx;
    for (int i = tid; i < 8 * 64 * 9; i += 256) {
        int g = i / 576, r = i % 576;          // r = ci*9 + tap
        sw[r * 8 + g] = wt[co0 * 576 + i];
    }
    int ox0 = blockIdx.x * 64, oy0 = blockIdx.y * 32;
    int ix0 = ox0 - pad, iy0 = oy0 - pad;
    float acc[8][2][4];
#pragma unroll
    for (int g = 0; g < 8; g++)
#pragma unroll
        for (int a = 0; a < 2; a++)
#pragma unroll
            for (int c = 0; c < 4; c++) acc[g][a][c] = 0.f;
    const float* inp0 = in + (size_t)b * 64 * Hin * Win;
    for (int i = tid; i < 34 * TW; i += 256) {
        int rr = i / TW, cc = i % TW;
        int r = iy0 + rr, c = ix0 + cc;
        sx[0][i] = (cc < 66 && r >= 0 && r < Hin && c >= 0 && c < Win)
                       ? inp0[(size_t)r * Win + c] : 0.f;
    }
    __syncthreads();
    int rb = ty * 2, cb = tx * 4;
    for (int ci = 0; ci < 64; ci++) {
        int cur = ci & 1;
        if (ci < 63) {
            const float* inp = inp0 + (size_t)(ci + 1) * Hin * Win;
            for (int i = tid; i < 34 * TW; i += 256) {
                int rr = i / TW, cc = i % TW;
                int r = iy0 + rr, c = ix0 + cc;
                sx[cur ^ 1][i] = (cc < 66 && r >= 0 && r < Hin && c >= 0 && c < Win)
                                     ? inp[(size_t)r * Win + c] : 0.f;
            }
        }
        float xr[4][6];
#pragma unroll
        for (int a = 0; a < 4; a++) {
            const float* rowp = &sx[cur][(rb + a) * TW + cb];
            float4 v4 = *reinterpret_cast<const float4*>(rowp);
            float2 v2 = *reinterpret_cast<const float2*>(rowp + 4);
            xr[a][0] = v4.x; xr[a][1] = v4.y; xr[a][2] = v4.z; xr[a][3] = v4.w;
            xr[a][4] = v2.x; xr[a][5] = v2.y;
        }
        const float* wbase = &sw[ci * 72];
#pragma unroll
        for (int t = 0; t < 9; t++) {
            int ky = t / 3, kx = t % 3;
            float4 wa = *reinterpret_cast<const float4*>(wbase + t * 8);
            float4 wb = *reinterpret_cast<const float4*>(wbase + t * 8 + 4);
            float w8[8] = {wa.x, wa.y, wa.z, wa.w, wb.x, wb.y, wb.z, wb.w};
#pragma unroll
            for (int g = 0; g < 8; g++)
#pragma unroll
                for (int py = 0; py < 2; py++)
#pragma unroll
                    for (int px = 0; px < 4; px++)
                        acc[g][py][px] += xr[py + ky][px + kx] * w8[g];
        }
        __syncthreads();
    }
#pragma unroll
    for (int g = 0; g < 8; g++) {
        int co = co0 + g;
        float sA = 1.f, sB = 0.f;
        if (useBN) { sA = gamma[co] * BN_SC; sB = beta[co]; }
        else if (beta) sB = beta[co];
#pragma unroll
        for (int py = 0; py < 2; py++)
#pragma unroll
            for (int px = 0; px < 4; px++) {
                int oy = oy0 + rb + py, ox = ox0 + cb + px;
                if (oy < Hout && ox < Wout) {
                    float v = acc[g][py][px] * sA + sB;
                    if (act == 1) v = fmaxf(v, 0.f);
                    else if (act == 2) v = fminf(fmaxf(v, 0.f), 6.f);
                    size_t oi = (size_t)(b * Cout_buf + co) * Hout * Wout +
                                (size_t)oy * Wout + ox;
                    if (prev) v += prev[oi];
                    out[oi] = v;
                }
            }
    }
}

// ---------- 3x3 conv stride 2 (w_gc), 8 co/block, transposed weights ----------
__global__ void __launch_bounds__(256, 2)
conv3x3s2_k(const float* __restrict__ in, const float* __restrict__ wt,
            const float* __restrict__ beta, float* __restrict__ out,
            int Hin, int Hout) {
    __shared__ __align__(16) float sw[64 * 9 * 8];   // [ci][tap][g]
    __shared__ __align__(16) float sx[65 * 65 + 3];
    int b = blockIdx.z >> 3;
    int co0 = (blockIdx.z & 7) << 3;
    int tid = threadIdx.y * 16 + threadIdx.x;
    for (int i = tid; i < 8 * 64 * 9; i += 256) {
        int g = i / 576, r = i % 576;
        sw[r * 8 + g] = wt[co0 * 576 + i];
    }
    int ox0 = blockIdx.x * 32, oy0 = blockIdx.y * 32;
    int ix0 = ox0 * 2, iy0 = oy0 * 2;
    float acc[8][2][2];
#pragma unroll
    for (int g = 0; g < 8; g++)
#pragma unroll
        for (int a = 0; a < 2; a++)
#pragma unroll
            for (int c = 0; c < 2; c++) acc[g][a][c] = 0.f;
    for (int ci = 0; ci < 64; ci++) {
        __syncthreads();
        const float* inp = in + (size_t)(b * 64 + ci) * Hin * Hin;
        for (int i = tid; i < 65 * 65; i += 256) {
            int r = iy0 + i / 65, c = ix0 + i % 65;
            sx[i] = (r < Hin && c < Hin) ? inp[(size_t)r * Hin + c] : 0.f;
        }
        __syncthreads();
        float xr[5][5];
        int rb = threadIdx.y * 4, cb = threadIdx.x * 4;
#pragma unroll
        for (int a = 0; a < 5; a++)
#pragma unroll
            for (int c = 0; c < 5; c++) xr[a][c] = sx[(rb + a) * 65 + cb + c];
        const float* wbase = &sw[ci * 72];
#pragma unroll
        for (int t = 0; t < 9; t++) {
            int ky = t / 3, kx = t % 3;
            float4 wa = *reinterpret_cast<const float4*>(wbase + t * 8);
            float4 wb = *reinterpret_cast<const float4*>(wbase + t * 8 + 4);
            float w8[8] = {wa.x, wa.y, wa.z, wa.w, wb.x, wb.y, wb.z, wb.w};
#pragma unroll
            for (int g = 0; g < 8; g++)
#pragma unroll
                for (int py = 0; py < 2; py++)
#pragma unroll
                    for (int px = 0; px < 2; px++)
                        acc[g][py][px] += xr[py * 2 + ky][px * 2 + kx] * w8[g];
        }
    }
#pragma unroll
    for (int g = 0; g < 8; g++) {
        int co = co0 + g;
        float sB = beta[co];
#pragma unroll
        for (int py = 0; py < 2; py++)
#pragma unroll
            for (int px = 0; px < 2; px++) {
                int oy = oy0 + threadIdx.y * 2 + py, ox = ox0 + threadIdx.x * 2 + px;
                if (oy < Hout && ox < Hout) {
                    float v = fmaxf(acc[g][py][px] + sB, 0.f);
                    out[(size_t)(b * 64 + co) * Hout * Hout + (size_t)oy * Hout + ox] = v;
                }
            }
    }
}

// ---------- 1x1 conv, 8 co/block, 4 contiguous px/thread, f32x2 ----------
__global__ void conv1x1_k(const float* __restrict__ in, const float* __restrict__ wt,
                          const float* __restrict__ gamma, const float* __restrict__ beta,
                          float* __restrict__ out,
                          int CoutW, int Cout_buf, int npix, int useBN) {
    __shared__ float swt[8 * 64];
    int ng = CoutW >> 3;
    int b = blockIdx.z / ng;
    int co0 = (blockIdx.z % ng) << 3;
    int tid = threadIdx.x;
    for (int i = tid; i < 512; i += 256) swt[i] = wt[co0 * 64 + i];
    __syncthreads();
    int base = blockIdx.x * 1024 + tid * 4;
    const float* inb = in + (size_t)b * 64 * npix + base;
    ull acc2[8][2];
#pragma unroll
    for (int c = 0; c < 8; c++) { acc2[c][0] = 0ULL; acc2[c][1] = 0ULL; }
    for (int ci = 0; ci < 64; ci++) {
        float4 x = *reinterpret_cast<const float4*>(inb + (size_t)ci * npix);
        ull xp0 = pk2(x.x, x.y), xp1 = pk2(x.z, x.w);
#pragma unroll
        for (int c = 0; c < 8; c++) {
            float w = swt[c * 64 + ci];
            ull wd = pk2(w, w);
            acc2[c][0] = fma2(xp0, wd, acc2[c][0]);
            acc2[c][1] = fma2(xp1, wd, acc2[c][1]);
        }
    }
#pragma unroll
    for (int c = 0; c < 8; c++) {
        int co = co0 + c;
        float sA = 1.f, sB = 0.f;
        if (useBN) { sA = gamma[co] * BN_SC; sB = beta[co]; }
        else if (beta) sB = beta[co];
        float a0, a1, a2, a3;
        upk2(acc2[c][0], a0, a1);
        upk2(acc2[c][1], a2, a3);
        float4 o;
        o.x = a0 * sA + sB; o.y = a1 * sA + sB;
        o.z = a2 * sA + sB; o.w = a3 * sA + sB;
        *reinterpret_cast<float4*>(out + (size_t)(b * Cout_buf + co) * npix + base) = o;
    }
}

// ---------- 1x1 conv + bias + log_softmax ----------
__global__ void conv1x1_lsm_k(const float* __restrict__ in, const float* __restrict__ wt,
                              const float* __restrict__ bias, float* __restrict__ out) {
    __shared__ float swt[4096];
    __shared__ float sb[64];
    int tid = threadIdx.x;
    for (int i = tid; i < 4096; i += 256) swt[i] = wt[i];
    if (tid < 64) sb[tid] = bias[tid];
    __syncthreads();
    int p = blockIdx.x * 256 + tid;
    int b = blockIdx.z;
    const float* inb = in + (size_t)b * 64 * HW;
    float acc[64];
#pragma unroll
    for (int c = 0; c < 64; c++) acc[c] = sb[c];
    for (int ci = 0; ci < 64; ci++) {
        float xv = inb[(size_t)ci * HW + p];
#pragma unroll
        for (int c = 0; c < 64; c++) acc[c] += swt[c * 64 + ci] * xv;
    }
    float m = -1e30f;
#pragma unroll
    for (int c = 0; c < 64; c++) m = fmaxf(m, acc[c]);
    float s = 0.f;
#pragma unroll
    for (int c = 0; c < 64; c++) s += __expf(acc[c] - m);
    float l = m + __logf(s);
#pragma unroll
    for (int c = 0; c < 64; c++) out[(size_t)(b * 64 + c) * HW + p] = acc[c] - l;
}

// ---------- forward row DFT, real -> half spectrum, n unrolled x2 ----------
__global__ void dftf_rows_k(const float* __restrict__ x, float* __restrict__ Are,
                            float* __restrict__ Aim) {
    __shared__ float sx[8 * H2];
    size_t row0 = (size_t)blockIdx.x * 8;
    int t = threadIdx.x;
    const float* xp = x + row0 * H2;
    for (int i = t; i < 8 * H2; i += 64) sx[i] = xp[i];
    __syncthreads();
    float ar[8], ai[8];
#pragma unroll
    for (int r = 0; r < 8; r++) { ar[r] = 0.f; ai[r] = 0.f; }
    for (int n = 0; n < H2; n += 2) {
        float wr0 = g_Wre[n * H2 + t], wi0 = g_Wim[n * H2 + t];
        float wr1 = g_Wre[(n + 1) * H2 + t], wi1 = g_Wim[(n + 1) * H2 + t];
#pragma unroll
        for (int r = 0; r < 8; r++) {
            float xv0 = sx[r * H2 + n];
            ar[r] += xv0 * wr0; ai[r] += xv0 * wi0;
            float xv1 = sx[r * H2 + n + 1];
            ar[r] += xv1 * wr1; ai[r] += xv1 * wi1;
        }
    }
#pragma unroll
    for (int r = 0; r < 8; r++) {
        Are[(row0 + r) * 64 + t] = ar[r];
        Aim[(row0 + r) * 64 + t] = ai[r];
    }
}

// ---------- column DFT, 16 k/block, h unrolled x2 with float2 twiddle LDS ----------
__global__ void dftc_k(const float* __restrict__ Xre, const float* __restrict__ Xim,
                       float* __restrict__ Ore, float* __restrict__ Oim,
                       float wisign, float scale, int domask) {
    __shared__ __align__(8) float swr[16 * H2], swi[16 * H2];
    int img = blockIdx.x;
    int k0 = blockIdx.y * 16;
    int nk = min(16, H2 - k0);
    int t = threadIdx.x;
    for (int i = t; i < 16 * H2; i += 64) {
        int kk = i / H2, h = i % H2;
        bool ok = (k0 + kk) < H2;
        swr[i] = ok ? g_Wre[(k0 + kk) * H2 + h] : 0.f;
        swi[i] = ok ? wisign * g_Wim[(k0 + kk) * H2 + h] : 0.f;
    }
    __syncthreads();
    const float* xr = Xre + (size_t)img * NH2;
    const float* xi = Xim + (size_t)img * NH2;
    int c2 = t - (t >= 63 ? 126 : 0);
    int c2sq = c2 * c2;
    float or_[16], oi_[16];
#pragma unroll
    for (int i = 0; i < 16; i++) { or_[i] = 0.f; oi_[i] = 0.f; }
    for (int h = 0; h < H2; h += 2) {
        float a0 = xr[h * 64 + t], b0 = xi[h * 64 + t];
        float a1 = xr[(h + 1) * 64 + t], b1 = xi[(h + 1) * 64 + t];
        if (domask) {
            int c1 = h - (h >= 63 ? 126 : 0);
            float f0m = (c1 * c1 + c2sq > 1600) ? sqrtf(a0 * a0 + b0 * b0) : 0.f;
            a0 *= f0m; b0 *= f0m;
            int c1b = (h + 1) - ((h + 1) >= 63 ? 126 : 0);
            float f1m = (c1b * c1b + c2sq > 1600) ? sqrtf(a1 * a1 + b1 * b1) : 0.f;
            a1 *= f1m; b1 *= f1m;
        }
#pragma unroll
        for (int i = 0; i < 16; i++) {
            float2 wr2 = *reinterpret_cast<const float2*>(&swr[i * H2 + h]);
            float2 wi2 = *reinterpret_cast<const float2*>(&swi[i * H2 + h]);
            or_[i] += a0 * wr2.x - b0 * wi2.x;
            oi_[i] += a0 * wi2.x + b0 * wr2.x;
            or_[i] += a1 * wr2.y - b1 * wi2.y;
            oi_[i] += a1 * wi2.y + b1 * wr2.y;
        }
    }
    float* pr = Ore + (size_t)img * NH2;
    float* pi = Oim + (size_t)img * NH2;
    for (int i = 0; i < nk; i++) {
        pr[(k0 + i) * 64 + t] = or_[i] * scale;
        pi[(k0 + i) * 64 + t] = oi_[i] * scale;
    }
}

// ---------- inverse row DFT via conjugate symmetry, t2 unrolled x2 ----------
__global__ void dfti_rows_mag_k(const float* __restrict__ Cre, const float* __restrict__ Cim,
                                const float* __restrict__ gbw, float* __restrict__ xc) {
    __shared__ float sre[8 * 64], sim[8 * 64];
    size_t row0 = (size_t)blockIdx.x * 8;
    int t = threadIdx.x;
    const float* pr = Cre + row0 * 64;
    const float* pi = Cim + row0 * 64;
    for (int i = t; i < 512; i += 128) { sre[i] = pr[i]; sim[i] = pi[i]; }
    __syncthreads();
    if (t >= H2) return;
    float acc[8];
#pragma unroll
    for (int r = 0; r < 8; r++) acc[r] = 0.f;
    for (int t2 = 1; t2 < 63; t2 += 2) {
        float wr0 = g_Wre[t2 * H2 + t], wi0 = g_Wim[t2 * H2 + t];
        float wr1 = g_Wre[(t2 + 1) * H2 + t], wi1 = g_Wim[(t2 + 1) * H2 + t];
#pragma unroll
        for (int r = 0; r < 8; r++) {
            acc[r] += sre[r * 64 + t2] * wr0 + sim[r * 64 + t2] * wi0;
            acc[r] += sre[r * 64 + t2 + 1] * wr1 + sim[r * 64 + t2 + 1] * wi1;
        }
    }
    float sgn = (t & 1) ? -1.f : 1.f;
    float wa = fmaxf(gbw[0], 0.f), wb = fmaxf(gbw[1], 0.f);
    float s = wa + wb + 1e-8f;
    float f0 = wa / s, f1 = wb / s;
#pragma unroll
    for (int r = 0; r < 8; r++) {
        float val = 2.f * acc[r] + sre[r * 64] + sgn * sre[r * 64 + 63];
        size_t idx = (row0 + r) * H2 + t;
        float mag = fabsf(val) * (1.f / 126.f);
        xc[idx] = f0 * mag + f1 * xc[idx];
    }
}

__global__ void maxpool_k(const float* __restrict__ in, float* __restrict__ out,
                          int Hin, int Hout, int stride, int total) {
    int idx = blockIdx.x * blockDim.x + threadIdx.x;
    if (idx >= total) return;
    int plane = idx / (Hout * Hout);
    int rc = idx % (Hout * Hout);
    int r = (rc / Hout) * stride, c = (rc % Hout) * stride;
    const float* p = in + (size_t)plane * Hin * Hin;
    out[idx] = fmaxf(fmaxf(p[r * Hin + c], p[r * Hin + c + 1]),
                     fmaxf(p[(r + 1) * Hin + c], p[(r + 1) * Hin + c + 1]));
}

__global__ void resize_k(const float* __restrict__ in, float* __restrict__ out) {
    int idx = blockIdx.x * blockDim.x + threadIdx.x;
    if (idx >= NPIX) return;
    int plane = idx >> 14;
    int ij = idx & 16383;
    int i = ij >> 7, j = ij & 127;
    const float* p = in + (size_t)plane * 961;
    const float sc = 31.f / 128.f;
    float fy = (i + 0.5f) * sc - 0.5f;
    int y0 = (int)floorf(fy);
    float wy = fy - (float)y0;
    int ya = min(max(y0, 0), 30), yb = min(max(y0 + 1, 0), 30);
    float fx = (j + 0.5f) * sc - 0.5f;
    int x0 = (int)floorf(fx);
    float wx = fx - (float)x0;
    int xa = min(max(x0, 0), 30), xb = min(max(x0 + 1, 0), 30);
    out[idx] = (1.f - wy) * ((1.f - wx) * p[ya * 31 + xa] + wx * p[ya * 31 + xb]) +
               wy * ((1.f - wx) * p[yb * 31 + xa] + wx * p[yb * 31 + xb]);
}

// ---------- windowed attention: 4 windows per 256-thread block ----------
__global__ void attn_k(const float* __restrict__ qkv, float* __restrict__ o) {
    __shared__ float sk[4][64 * 8], sv[4][64 * 8];
    int sub = threadIdx.x >> 6;
    int t = threadIdx.x & 63;
    int win = blockIdx.x * 4 + sub;
    int head = blockIdx.y, b = blockIdx.z;
    int gi = win >> 4, gj = win & 15;
    int wi = t >> 3, wj = t & 7;
    int pix = ((gi * 8 + wi) << 7) + gj * 8 + wj;
    size_t base = (size_t)b * 192 * HW;
    float q[8];
#pragma unroll
    for (int d = 0; d < 8; d++) {
        int ch = head * 8 + d;
        q[d] = qkv[base + (size_t)ch * HW + pix] * ATT_SCALE;
        sk[sub][t * 8 + d] = qkv[base + (size_t)(64 + ch) * HW + pix];
        sv[sub][t * 8 + d] = qkv[base + (size_t)(128 + ch) * HW + pix];
    }
    __syncthreads();
    const float* rp = g_rpb + (head * 64 + t) * 64;
    float dots[64];
    float m = -1e30f;
    for (int j = 0; j < 64; j++) {
        float s = rp[j];
#pragma unroll
        for (int d = 0; d < 8; d++) s += q[d] * sk[sub][j * 8 + d];
        dots[j] = s;
        m = fmaxf(m, s);
    }
    float sum = 0.f;
    for (int j = 0; j < 64; j++) { dots[j] = __expf(dots[j] - m); sum += dots[j]; }
    float inv = 1.f / sum;
    float acc[8];
#pragma unroll
    for (int d = 0; d < 8; d++) acc[d] = 0.f;
    for (int j = 0; j < 64; j++) {
        float a = dots[j] * inv;
#pragma unroll
        for (int d = 0; d < 8; d++) acc[d] += a * sv[sub][j * 8 + d];
    }
#pragma unroll
    for (int d = 0; d < 8; d++)
        o[(size_t)(b * 64 + head * 8 + d) * HW + pix] = acc[d];
}

__global__ void pooladd_k(const float* __restrict__ o, const float* __restrict__ loc,
                          float* __restrict__ out) {
    int idx = blockIdx.x * blockDim.x + threadIdx.x;
    if (idx >= NPIX) return;
    int plane = idx >> 14;
    int ij = idx & 16383;
    int i = ij >> 7, j = ij & 127;
    const float* p = o + (size_t)plane * HW;
    float sx = 0.f, sy = 0.f;
#pragma unroll
    for (int d = -3; d <= 4; d++) {
        int r = i + d;
        if (r >= 0 && r <= 128) sx += p[(r == 128 ? 126 : r) * 128 + j];
        int c = j + d;
        if (c >= 0 && c <= 128) sy += p[i * 128 + (c == 128 ? 126 : c)];
    }
    out[idx] = sx * 0.125f + sy * 0.125f + loc[idx];
}

__global__ void dwconv_k(const float* __restrict__ in, const float* __restrict__ wdw,
                         const float* __restrict__ g, const float* __restrict__ bb,
                         float* __restrict__ out) {
    __shared__ float sx[23 * 23];
    __shared__ float sw[64];
    int c = blockIdx.z & 63, b = blockIdx.z >> 6;
    int tid = threadIdx.y * 16 + threadIdx.x;
    if (tid < 64) sw[tid] = wdw[c * 64 + tid];
    const float* p = in + (size_t)(b * 64 + c) * HW;
    int iy0 = blockIdx.y * 16 - 3, ix0 = blockIdx.x * 16 - 3;
    for (int i = tid; i < 529; i += 256) {
        int r = iy0 + i / 23, cc = ix0 + i % 23;
        sx[i] = (r >= 0 && r < 128 && cc >= 0 && cc < 128) ? p[r * 128 + cc] : 0.f;
    }
    __syncthreads();
    float acc = 0.f;
#pragma unroll
    for (int ky = 0; ky < 8; ky++)
#pragma unroll
        for (int kx = 0; kx < 8; kx++)
            acc += sx[(threadIdx.y + ky) * 23 + threadIdx.x + kx] * sw[ky * 8 + kx];
    int oy = blockIdx.y * 16 + threadIdx.y, ox = blockIdx.x * 16 + threadIdx.x;
    out[(size_t)(b * 64 + c) * HW + oy * 128 + ox] = acc * (g[c] * BN_SC) + bb[c];
}

extern "C" void kernel_launch(void* const* d_in, const int* in_sizes, int n_in,
                              void* d_out, int out_size) {
    const float* x = (const float*)d_in[0];
    const float* w_qkv = (const float*)d_in[1];
    const float* w_l1 = (const float*)d_in[2];
    const float* g_l1 = (const float*)d_in[3];
    const float* b_l1 = (const float*)d_in[4];
    const float* w_l2 = (const float*)d_in[5];
    const float* g_l2 = (const float*)d_in[6];
    const float* b_l2 = (const float*)d_in[7];
    const float* f_cos = (const float*)d_in[8];
    const float* f_sin = (const float*)d_in[9];
    const float* gb_b1 = (const float*)d_in[10];
    const float* gb_b2 = (const float*)d_in[11];
    const float* gb_w = (const float*)d_in[12];
    const float* w_post = (const float*)d_in[13];
    const float* g_post = (const float*)d_in[14];
    const float* b_post = (const float*)d_in[15];
    const float* w_gc = (const float*)d_in[16];
    const float* b_gc = (const float*)d_in[17];
    const float* w_gc1 = (const float*)d_in[18];
    const float* b_gc1 = (const float*)d_in[19];
    const float* w_gc2 = (const float*)d_in[20];
    const float* b_gc2 = (const float*)d_in[21];
    const float* rpb_table = (const float*)d_in[22];
    const float* w_dw = (const float*)d_in[23];
    const float* g_proj = (const float*)d_in[24];
    const float* b_proj = (const float*)d_in[25];
    const float* w_pw = (const float*)d_in[26];
    const int* rel_index = (const int*)d_in[27];

    float *buf1, *buf2, *buf3, *qkvb, *xc, *Are, *Aim, *Bre, *Bim, *wpack, *bpack;
    cudaGetSymbolAddress((void**)&buf1, g_buf1);
    cudaGetSymbolAddress((void**)&buf2, g_buf2);
    cudaGetSymbolAddress((void**)&buf3, g_buf3);
    cudaGetSymbolAddress((void**)&qkvb, g_qkv);
    cudaGetSymbolAddress((void**)&xc, g_xc);
    cudaGetSymbolAddress((void**)&Are, g_Are);
    cudaGetSymbolAddress((void**)&Aim, g_Aim);
    cudaGetSymbolAddress((void**)&Bre, g_Bre);
    cudaGetSymbolAddress((void**)&Bim, g_Bim);
    cudaGetSymbolAddress((void**)&wpack, g_wpack);
    cudaGetSymbolAddress((void**)&bpack, g_bpack);

    dim3 thr2(16, 16);
    init_w126_k<<<(HW126 + 255) / 256, 256>>>();
    init_rpb_k<<<128, 256>>>(rpb_table, rel_index);
    pack_gabor_k<<<72, 256>>>(f_cos, f_sin, gb_b1, gb_b2);

    // local = bn(conv1x1) + bn(conv3x3)
    conv1x1_k<<<dim3(16, 1, 64), 256>>>(x, w_l2, g_l2, b_l2, buf1, 64, 64, HW, 1);
    conv3x3s1_k<<<dim3(2, 4, 64), thr2>>>(x, w_l1, g_l1, b_l1, buf1, buf1,
                                          64, 64, 128, 128, 128, 128, 1, 0, 1);
    // fused gabor convs (valid, 126x126)
    conv3x3s1_k<<<dim3(2, 4, 64), thr2>>>(buf1, wpack, nullptr, bpack, nullptr, xc,
                                          64, 64, 128, 128, 126, 126, 0, 0, 0);
    // FFT high-pass (half spectrum, mask fused into inverse col pass)
    dftf_rows_k<<<8064, 64>>>(xc, Are, Aim);
    dftc_k<<<dim3(512, 8), 64>>>(Are, Aim, Bre, Bim, 1.f, 1.f, 0);
    dftc_k<<<dim3(512, 8), 64>>>(Bre, Bim, Are, Aim, -1.f, 1.f / 126.f, 1);
    dfti_rows_mag_k<<<8064, 128>>>(Are, Aim, gb_w, xc);
    // post conv + relu6
    conv3x3s1_k<<<dim3(2, 4, 64), thr2>>>(xc, w_post, g_post, b_post, nullptr, Are,
                                          64, 64, 126, 126, 126, 126, 1, 2, 1);
    maxpool_k<<<(8000000 + 255) / 256, 256>>>(Are, Bre, 126, 125, 1, 8000000);
    conv3x3s2_k<<<dim3(2, 2, 64), thr2>>>(Bre, w_gc, b_gc, Aim, 125, 62);
    maxpool_k<<<(492032 + 255) / 256, 256>>>(Aim, Bim, 62, 31, 2, 492032);
    resize_k<<<NPIX / 256, 256>>>(Bim, buf2);
    conv3x3s1_k<<<dim3(2, 4, 64), thr2>>>(buf2, w_gc1, nullptr, b_gc1, nullptr, buf3,
                                          64, 64, 128, 128, 128, 128, 1, 1, 0);
    conv1x1_lsm_k<<<dim3(64, 1, 8), 256>>>(buf3, w_gc2, b_gc2, buf1);
    // global branch
    conv1x1_k<<<dim3(16, 1, 192), 256>>>(x, w_qkv, nullptr, nullptr, qkvb, 192, 192, HW, 0);
    attn_k<<<dim3(64, 8, 8), 256>>>(qkvb, buf2);
    pooladd_k<<<NPIX / 256, 256>>>(buf2, buf1, buf3);
    // projection
    dwconv_k<<<dim3(8, 8, 512), thr2>>>(buf3, w_dw, g_proj, b_proj, buf2);
    conv1x1_k<<<dim3(16, 1, 64), 256>>>(buf2, w_pw, nullptr, nullptr, (float*)d_out,
                                        64, 64, HW, 0);
}